// round 11
// baseline (speedup 1.0000x reference)
#include <cuda_runtime.h>
#include <cuda_bf16.h>
#include <cstdint>

// Embedding gather + sinusoidal positional encoding.
// out[row, c] = W[ids[row], c] + (row even ? sin : cos)(row * freq(c)),
//   freq(c) = 10000^(-2c/D)
//
// D = 1024, TOKENS = 8192. Grid = 2048 CTAs x 4 rows, 256 threads (best shape).
// PE for the 4 rows computed INDEPENDENTLY by angle addition from one
// (sin,cos) seed pair — no serial rotor chain between the 4 stores:
//   sin(a)      = s0
//   cos(a+d)    = c0*cd - s0*sd
//   sin(a+2d)   = s0*c2d + c0*s2d     (s2d,c2d via double angle)
//   cos(a+3d)   = c0*c3d - s0*s3d     (s3d,c3d via triple angle)
// Seeds via Cody-Waite reduction + MUFU __sinf/__cosf.

static constexpr int D       = 1024;
static constexpr int VEC     = 4;
static constexpr int THREADS = D / VEC;   // 256
static constexpr int R       = 4;         // rows per block

// sincos for 0 <= x <= ~8200: 3-term Cody-Waite reduction mod 2*pi, then MUFU.
__device__ __forceinline__ void fast_sincos(float x, float& s, float& c)
{
    const float INV2PI = 0.15915494309189535f;
    const float C1 = 6.28125f;
    const float C2 = 1.93530717957e-3f;
    const float C3 = 6.1232339957e-10f;
    float q = rintf(x * INV2PI);
    float a = fmaf(-q, C1, x);
    a = fmaf(-q, C2, a);
    a = fmaf(-q, C3, a);
    s = __sinf(a);
    c = __cosf(a);
}

__global__ __launch_bounds__(THREADS, 6)
void emb_pe_kernel(const int* __restrict__ ids,
                   const float* __restrict__ W,
                   float* __restrict__ out)
{
    const int row0 = blockIdx.x * R;          // multiple of 4 -> even
    const int t    = threadIdx.x;             // 0..255
    const int c0   = t * VEC;                 // starting column

    // One 16B load covers this CTA's 4 ids (aligned since row0 % 4 == 0).
    const int4 ii = *reinterpret_cast<const int4*>(ids + row0);

    const float* Wc = W + c0;

    // Front-batch all 4 gathers (independent LDG.128, MLP=4).
    const float4 v0 = *reinterpret_cast<const float4*>(Wc + (size_t)ii.x * D);
    const float4 v1 = *reinterpret_cast<const float4*>(Wc + (size_t)ii.y * D);
    const float4 v2 = *reinterpret_cast<const float4*>(Wc + (size_t)ii.z * D);
    const float4 v3 = *reinterpret_cast<const float4*>(Wc + (size_t)ii.w * D);

    // PE (overlaps gather latency).
    // freq(c) = 2^(kexp * c),  kexp = -2*log2(10000)/D
    const float kexp = -13.287712379549449f * 2.0f / (float)D;
    const float pos0 = (float)row0;

    float pe0[VEC], pe1[VEC], pe2[VEC], pe3[VEC];
#pragma unroll
    for (int i = 0; i < VEC; i++) {
        float freq = exp2f(kexp * (float)(c0 + i));
        float s0, c0r, sd, cd;
        fast_sincos(pos0 * freq, s0, c0r);    // seed at row0
        fast_sincos(freq,        sd, cd);     // +1 row delta
        // double / triple angle (pure FMA):
        float s2d = 2.0f * sd * cd;
        float c2d = fmaf(-2.0f * sd, sd, 1.0f);
        float s3d = fmaf(s2d, cd,  c2d * sd);
        float c3d = fmaf(c2d, cd, -s2d * sd);
        // independent per-row PE values:
        pe0[i] = s0;                               // sin(row0 * f)
        pe1[i] = fmaf(c0r, cd, -s0 * sd);          // cos((row0+1) f)
        pe2[i] = fmaf(s0, c2d,  c0r * s2d);        // sin((row0+2) f)
        pe3[i] = fmaf(c0r, c3d, -s0 * s3d);        // cos((row0+3) f)
    }

    float* outp = out + (size_t)row0 * D + c0;
    float4 o;

    o.x = v0.x + pe0[0]; o.y = v0.y + pe0[1]; o.z = v0.z + pe0[2]; o.w = v0.w + pe0[3];
    *reinterpret_cast<float4*>(outp) = o;

    o.x = v1.x + pe1[0]; o.y = v1.y + pe1[1]; o.z = v1.z + pe1[2]; o.w = v1.w + pe1[3];
    *reinterpret_cast<float4*>(outp + D) = o;

    o.x = v2.x + pe2[0]; o.y = v2.y + pe2[1]; o.z = v2.z + pe2[2]; o.w = v2.w + pe2[3];
    *reinterpret_cast<float4*>(outp + 2 * D) = o;

    o.x = v3.x + pe3[0]; o.y = v3.y + pe3[1]; o.z = v3.z + pe3[2]; o.w = v3.w + pe3[3];
    *reinterpret_cast<float4*>(outp + 3 * D) = o;
}

extern "C" void kernel_launch(void* const* d_in, const int* in_sizes, int n_in,
                              void* d_out, int out_size)
{
    const int*   ids = (const int*)d_in[0];
    const float* W   = (const float*)d_in[1];
    float*       out = (float*)d_out;

    const int rows = in_sizes[0];             // 8192 tokens
    emb_pe_kernel<<<rows / R, THREADS>>>(ids, W, out);
}